// round 2
// baseline (speedup 1.0000x reference)
#include <cuda_runtime.h>
#include <math.h>

// Problem constants
#define NC   21
#define HW   (512 * 512)        // 262144 = 2^18
#define NB   8
#define NPIX (NB * HW)          // 2,097,152 pixels

// Global scratch (allocation-free rule: __device__ globals)
__device__ float g_cls_sum[NC];
__device__ int   g_cls_cnt[NC];

__global__ void cbfocal_zero_kernel() {
    int i = threadIdx.x;
    if (i < NC) {
        g_cls_sum[i] = 0.0f;
        g_cls_cnt[i] = 0;
    }
}

__global__ __launch_bounds__(256, 4)
void cbfocal_main_kernel(const float* __restrict__ pred,
                         const float* __restrict__ target) {
    __shared__ float s_sum[NC];
    __shared__ int   s_cnt[NC];

    int t = threadIdx.x;
    if (t < NC) {
        s_sum[t] = 0.0f;
        s_cnt[t] = 0;
    }
    __syncthreads();

    // One thread per pixel; grid is exact (8192 * 256 == NPIX)
    long i  = (long)blockIdx.x * 256 + t;
    int  b  = (int)(i >> 18);          // i / HW
    int  hw = (int)(i & (HW - 1));     // i % HW

    const float* pp = pred   + (((long)b * NC) << 18) + hw;
    const float* tp = target + (((long)b * NC) << 18) + hw;

    // Load all channels: track max, capture the one-hot class branchlessly.
    float v[NC];
    float m   = -1e30f;
    float vc  = 0.0f;
    int   cls = 0;
    #pragma unroll
    for (int c = 0; c < NC; c++) {
        float pv = pp[(long)c << 18];
        float tv = tp[(long)c << 18];
        v[c] = pv;
        m = fmaxf(m, pv);
        bool hit = (tv > 0.5f);
        cls = hit ? c  : cls;
        vc  = hit ? pv : vc;
    }

    // log-sum-exp
    float s = 0.0f;
    #pragma unroll
    for (int c = 0; c < NC; c++) {
        s += __expf(v[c] - m);
    }
    float lse = m + __logf(s);

    float lp = vc - lse;          // log p_cls
    float p  = __expf(lp);        // p_cls
    float om = 1.0f - p;
    float rv = om * om * lp;      // (1-p)^gamma * log p, gamma = 2

    atomicAdd(&s_sum[cls], rv);
    atomicAdd(&s_cnt[cls], 1);
    __syncthreads();

    if (t < NC) {
        atomicAdd(&g_cls_sum[t], s_sum[t]);
        atomicAdd(&g_cls_cnt[t], s_cnt[t]);
    }
}

__global__ void cbfocal_final_kernel(float* __restrict__ out) {
    int c = threadIdx.x;  // one warp
    const double n    = (double)NPIX;
    const double beta = (n - 1.0) / n;

    double val = 0.0;
    if (c < NC) {
        double nc = (double)g_cls_cnt[c];
        double w  = (1.0 - beta) / (1.0 - pow(beta, nc) + 1e-6);
        val = w * (double)g_cls_sum[c];
    }
    #pragma unroll
    for (int o = 16; o > 0; o >>= 1) {
        val += __shfl_down_sync(0xffffffffu, val, o);
    }
    if (c == 0) {
        out[0] = (float)(-val / n);
    }
}

extern "C" void kernel_launch(void* const* d_in, const int* in_sizes, int n_in,
                              void* d_out, int out_size) {
    const float* pred   = (const float*)d_in[0];
    const float* target = (const float*)d_in[1];
    float* out = (float*)d_out;

    cbfocal_zero_kernel<<<1, 32>>>();
    cbfocal_main_kernel<<<NPIX / 256, 256>>>(pred, target);
    cbfocal_final_kernel<<<1, 32>>>(out);
}